// round 15
// baseline (speedup 1.0000x reference)
#include <cuda_runtime.h>
#include <cuda_fp16.h>
#include <cuda_bf16.h>
#include <mma.h>
#include <math.h>

using namespace nvcuda;

#define BATCH 64
#define HID   1024
#define EMB   256
#define VOC   32000
#define G4    4096
#define KC    1280
#define SRCLEN 64
#define TRGLEN 64
#define NCTA  128
#define NTHR  512

#define WLD   1288
#define ALD2  40        // LSTM 32-K chunk ld (bf16)
#define HLD2  40        // fc h 32-K chunk ld (fp16)
#define SGLD  36
#define PLD   20

#define OFF_W    0
#define SZ_W     (2*32*WLD*2)            // 164,864
#define OFF_DYN  SZ_W
#define L_STG_B  (2*2*64*ALD2*2)         // 20,480 per LSTM stage (3 stages = 61,440)
#define F_STG_B  (64*HLD2*2)             // 5,120 per fc H stage (3 stages)
#define DYN_SZ   61440
#define OFF_C    (OFF_DYN + DYN_SZ)      // 226,304
#define SMEM_TOTAL (OFF_C + 2048)        // 228,352

// LSTM position->chunk order: h chunks (8..19) first, x chunks (0..7) last
#define ORD(i) (((i) < 12) ? ((i) + 8) : ((i) - 12))

// ---------------- device scratch ----------------
__device__ __align__(16) __half        g_W16[(size_t)VOC * HID];
__device__ __align__(16) __nv_bfloat16 g_Wl_hi[2 * (size_t)G4 * KC];
__device__ __align__(16) __nv_bfloat16 g_Wl_lo[2 * (size_t)G4 * KC];
__device__ __align__(16) float         g_bias[2 * G4];
__device__ __align__(16) float         g_h[2][BATCH * HID];   // parity-buffered fp32 h
__device__ __align__(16) __half        g_h16[BATCH * HID];
__device__ __align__(16) __nv_bfloat16 g_A_hi[2][BATCH * KC];
__device__ __align__(16) __nv_bfloat16 g_A_lo[2][BATCH * KC];
__device__ unsigned g_pmax[NCTA * BATCH];
__device__ unsigned g_flag[NCTA * 32];
__device__ unsigned g_xcnt;             // decoder x-staging counter (64 per step)

// ---------------- helpers ----------------
__device__ __forceinline__ void cpa16(void* dst, const void* src) {
    unsigned d = (unsigned)__cvta_generic_to_shared(dst);
    asm volatile("cp.async.cg.shared.global [%0], [%1], 16;\n" :: "r"(d), "l"(src));
}
__device__ __forceinline__ void cp_commit() { asm volatile("cp.async.commit_group;\n"); }
template<int N> __device__ __forceinline__ void cp_wait() {
    asm volatile("cp.async.wait_group %0;\n" :: "n"(N));
}
__device__ __forceinline__ unsigned fenc(float f) {
    unsigned u = __float_as_uint(f);
    return (u & 0x80000000u) ? ~u : (u | 0x80000000u);
}
__device__ __forceinline__ float fdec(unsigned k) {
    return (k & 0x80000000u) ? __uint_as_float(k & 0x7fffffffu) : __uint_as_float(~k);
}
__device__ __forceinline__ unsigned ld_acq(const unsigned* p) {
    unsigned v;
    asm volatile("ld.acquire.gpu.global.u32 %0, [%1];" : "=r"(v) : "l"(p));
    return v;
}
__device__ __forceinline__ void st_rel(unsigned* p, unsigned v) {
    asm volatile("st.release.gpu.global.u32 [%0], %1;" :: "l"(p), "r"(v));
}
__device__ __forceinline__ void red_add_rel(unsigned* p, unsigned v) {
    asm volatile("red.add.release.gpu.global.u32 [%0], %1;" :: "l"(p), "r"(v));
}
__device__ __forceinline__ void gbar(unsigned gen) {
    __syncthreads();
    if (threadIdx.x == 0) st_rel(&g_flag[blockIdx.x * 32], gen);
    if (threadIdx.x < NCTA) {
        while (ld_acq(&g_flag[threadIdx.x * 32]) < gen) { }
    }
    __syncthreads();
}

// ---------------- prep kernels ----------------
__global__ void prep_fc(const float* __restrict__ W) {
    size_t stride = (size_t)gridDim.x * blockDim.x;
    for (size_t i = (size_t)blockIdx.x * blockDim.x + threadIdx.x;
         i < (size_t)VOC * HID; i += stride)
        g_W16[i] = __float2half(W[i]);
}

__global__ void prep_lstm(const float* __restrict__ eWih, const float* __restrict__ eWhh,
                          const float* __restrict__ ebih, const float* __restrict__ ebhh,
                          const float* __restrict__ dWih, const float* __restrict__ dWhh,
                          const float* __restrict__ dbih, const float* __restrict__ dbhh) {
    size_t stride = (size_t)gridDim.x * blockDim.x;
    size_t gid0 = (size_t)blockIdx.x * blockDim.x + threadIdx.x;
    const size_t per = (size_t)G4 * KC;
    for (size_t i = gid0; i < 2 * per; i += stride) {
        int sel = (int)(i / per);
        size_t rem = i - (size_t)sel * per;
        int r = (int)(rem / KC);
        int k = (int)(rem % KC);
        int j = r >> 2, gate = r & 3;
        int orow = gate * HID + j;
        const float* Wih = sel ? dWih : eWih;
        const float* Whh = sel ? dWhh : eWhh;
        float v = (k < EMB) ? Wih[(size_t)orow * EMB + k]
                            : Whh[(size_t)orow * HID + (k - EMB)];
        __nv_bfloat16 hi = __float2bfloat16(v);
        g_Wl_hi[i] = hi;
        g_Wl_lo[i] = __float2bfloat16(v - __bfloat162float(hi));
    }
    for (size_t i = gid0; i < 2 * G4; i += stride) {
        int sel = (int)(i / G4);
        int r = (int)(i % G4);
        int j = r >> 2, gate = r & 3;
        int orow = gate * HID + j;
        g_bias[i] = sel ? (dbih[orow] + dbhh[orow]) : (ebih[orow] + ebhh[orow]);
    }
}

__global__ void init_k(float* __restrict__ out) {
    size_t stride = (size_t)gridDim.x * blockDim.x;
    size_t g0 = (size_t)blockIdx.x * blockDim.x + threadIdx.x;
    for (size_t i = g0; i < (size_t)BATCH * VOC; i += stride) out[i] = 0.f;
    for (size_t i = g0; i < (size_t)64 * 1024; i += stride) {
        int b = (int)(i >> 10), j = (int)(i & 1023);
        g_A_hi[0][b * KC + EMB + j] = __float2bfloat16(0.f);
        g_A_lo[0][b * KC + EMB + j] = __float2bfloat16(0.f);
    }
    if (g0 < NCTA * 32) g_flag[g0] = 0u;
    if (g0 == 0) g_xcnt = 0u;
}

// ---------------- weight load into smem ----------------
__device__ __forceinline__ void load_weights_dev(char* sm, int sel) {
    const int tid = threadIdx.x, cta = blockIdx.x;
    __nv_bfloat16* sWhi = (__nv_bfloat16*)(sm + OFF_W);
    __nv_bfloat16* sWlo = sWhi + 32 * WLD;
    const __nv_bfloat16* gh = g_Wl_hi + (size_t)sel * G4 * KC + (size_t)cta * 32 * KC;
    const __nv_bfloat16* gl = g_Wl_lo + (size_t)sel * G4 * KC + (size_t)cta * 32 * KC;
    for (int o = tid; o < 32 * 160; o += NTHR) {
        int r = o / 160, g = o % 160;
        *(float4*)(sWhi + r * WLD + g * 8) = *(const float4*)(gh + (size_t)r * KC + g * 8);
        *(float4*)(sWlo + r * WLD + g * 8) = *(const float4*)(gl + (size_t)r * KC + g * 8);
    }
    __syncthreads();
}

// ---------------- LSTM phase ----------------
// stage layout (bf16 elems): [ks(2)][mat(2)][r(64)][ALD2]
__device__ __forceinline__ void lstm_issue(char* sm, const __nv_bfloat16* gAh,
                                           const __nv_bfloat16* gAl, int c, int st) {
    __nv_bfloat16* base = (__nv_bfloat16*)(sm + OFF_DYN + st * L_STG_B);
    const int tid = threadIdx.x;
    #pragma unroll
    for (int j = 0; j < 2; j++) {
        int o = tid + j * NTHR;
        int ks = o >> 9;
        int rem = o & 511;
        int mat = rem >> 8;
        int rem2 = rem & 255;
        int r = rem2 >> 2, kg = rem2 & 3;
        int k0 = ks * 640 + c * 32;
        const __nv_bfloat16* src = (mat ? gAl : gAh) + (size_t)r * KC + k0 + kg * 8;
        cpa16(base + ks * 5120 + mat * 2560 + r * ALD2 + kg * 8, src);
    }
    cp_commit();
}

__device__ __forceinline__ void lstm_step_dev(char* sm, int p, int sel,
                                              int nx_tok, const float* nx_emb,
                                              int xtag) {
    const int tid = threadIdx.x, cta = blockIdx.x;
    const int warp = tid >> 5;
    const int mw = warp & 3, cw = (warp >> 2) & 1, ks = warp >> 3;
    __nv_bfloat16* sWhi = (__nv_bfloat16*)(sm + OFF_W);
    __nv_bfloat16* sWlo = sWhi + 32 * WLD;
    float* sC = (float*)(sm + OFF_C);

    const __nv_bfloat16* gAh = g_A_hi[p];
    const __nv_bfloat16* gAl = g_A_lo[p];

    wmma::fragment<wmma::accumulator, 16, 16, 16, float> a_hh, a_hl, a_lh;
    wmma::fill_fragment(a_hh, 0.f);
    wmma::fill_fragment(a_hl, 0.f);
    wmma::fill_fragment(a_lh, 0.f);

    lstm_issue(sm, gAh, gAl, ORD(0), 0);
    lstm_issue(sm, gAh, gAl, ORD(1), 1);
    for (int c = 0; c < 20; c++) {
        if (c < 19) cp_wait<1>(); else cp_wait<0>();
        // gate before issuing the first x-dependent chunk (ORD(12)=0 issued at c==10)
        if (xtag > 0 && c == 10) {
            if ((tid & 31) == 0) {
                while (ld_acq(&g_xcnt) < (unsigned)(64 * xtag)) __nanosleep(40);
            }
            __syncwarp();
        }
        __syncthreads();
        if (c + 2 < 20) lstm_issue(sm, gAh, gAl, ORD(c + 2), (c + 2) % 3);
        const int oc = ORD(c);
        const __nv_bfloat16* Ahi =
            (const __nv_bfloat16*)(sm + OFF_DYN + (c % 3) * L_STG_B) + ks * 5120 + mw * 16 * ALD2;
        const __nv_bfloat16* Alo = Ahi + 2560;
        #pragma unroll
        for (int ktl = 0; ktl < 2; ktl++) {
            wmma::fragment<wmma::matrix_a, 16, 16, 16, __nv_bfloat16, wmma::row_major> ahi, alo;
            wmma::fragment<wmma::matrix_b, 16, 16, 16, __nv_bfloat16, wmma::col_major> bhi, blo;
            wmma::load_matrix_sync(ahi, Ahi + ktl * 16, ALD2);
            wmma::load_matrix_sync(alo, Alo + ktl * 16, ALD2);
            int kk = ks * 640 + oc * 32 + ktl * 16;
            wmma::load_matrix_sync(bhi, sWhi + cw * 16 * WLD + kk, WLD);
            wmma::load_matrix_sync(blo, sWlo + cw * 16 * WLD + kk, WLD);
            wmma::mma_sync(a_hh, ahi, bhi, a_hh);
            wmma::mma_sync(a_hl, ahi, blo, a_hl);
            wmma::mma_sync(a_lh, alo, bhi, a_lh);
        }
    }
    #pragma unroll
    for (int i = 0; i < a_hh.num_elements; i++)
        a_hh.x[i] += a_hl.x[i] + a_lh.x[i];

    __syncthreads();
    float* sgP = (float*)(sm + OFF_DYN) + ks * (64 * SGLD);
    wmma::store_matrix_sync(sgP + mw * 16 * SGLD + cw * 16, a_hh, SGLD, wmma::mem_row_major);
    __syncthreads();

    const float* bias = g_bias + sel * G4 + cta * 32;
    float* sg0 = (float*)(sm + OFF_DYN);
    float* sg1 = sg0 + 64 * SGLD;
    int q = p ^ 1;
    __nv_bfloat16* oAh = g_A_hi[q];
    __nv_bfloat16* oAl = g_A_lo[q];
    {
        int e = tid;                       // 512 = 64 rows x 8 h-units
        int b = e >> 3, jj = e & 7;
        float gi = sg0[b * SGLD + jj * 4 + 0] + sg1[b * SGLD + jj * 4 + 0] + bias[jj * 4 + 0];
        float gf = sg0[b * SGLD + jj * 4 + 1] + sg1[b * SGLD + jj * 4 + 1] + bias[jj * 4 + 1];
        float gg = sg0[b * SGLD + jj * 4 + 2] + sg1[b * SGLD + jj * 4 + 2] + bias[jj * 4 + 2];
        float go = sg0[b * SGLD + jj * 4 + 3] + sg1[b * SGLD + jj * 4 + 3] + bias[jj * 4 + 3];
        float cold = sC[e];
        float si = 1.f / (1.f + expf(-gi));
        float sf = 1.f / (1.f + expf(-gf));
        float so = 1.f / (1.f + expf(-go));
        float cn = sf * cold + si * tanhf(gg);
        float hn = so * tanhf(cn);
        sC[e] = cn;
        int j = cta * 8 + jj;
        g_h[q][b * HID + j] = hn;
        g_h16[b * HID + j] = __float2half(hn);
        __nv_bfloat16 hi = __float2bfloat16(hn);
        oAh[b * KC + EMB + j] = hi;
        oAl[b * KC + EMB + j] = __float2bfloat16(hn - __bfloat162float(hi));
    }
    if (nx_tok >= 0 && cta < 64) {
        for (int k = tid; k < EMB; k += NTHR) {
            float v = nx_emb[(size_t)nx_tok * EMB + k];
            __nv_bfloat16 hi = __float2bfloat16(v);
            oAh[cta * KC + k] = hi;
            oAl[cta * KC + k] = __float2bfloat16(v - __bfloat162float(hi));
        }
    }
}

// ---------------- fc phase: 2m x 2n warp tiling, B direct from global, 32-K H chunks ----------------
__device__ __forceinline__ void fc_issueH(char* sm, int c, int st) {
    const int tid = threadIdx.x;
    __half* Hs = (__half*)(sm + OFF_DYN + st * F_STG_B);
    if (tid < 256) {
        int r = tid >> 2, g = tid & 3;
        cpa16(Hs + r * HLD2 + g * 8, g_h16 + r * HID + c * 32 + g * 8);
    }
    cp_commit();
}

__device__ __forceinline__ void fc_step_dev(char* sm, int t, const float* fcb,
                                            float* __restrict__ out) {
    const int tid = threadIdx.x, cta = blockIdx.x;
    const int warp = tid >> 5, lane = tid & 31;

    if (cta >= 125) {
        if (tid < 64) g_pmax[cta * 64 + tid] = 0u;
        return;
    }
    const int mh = warp & 1;      // m-half: m-tiles {mh*2, mh*2+1}
    const int n8 = warp >> 1;     // n-pair: cols n8*32 .. n8*32+31
    const __half* Wb = g_W16 + (size_t)(cta * 256 + n8 * 32) * HID;

    wmma::fragment<wmma::accumulator, 16, 16, 16, float> acc[2][2];
    #pragma unroll
    for (int mt = 0; mt < 2; mt++)
        #pragma unroll
        for (int nt = 0; nt < 2; nt++) wmma::fill_fragment(acc[mt][nt], 0.f);

    fc_issueH(sm, 0, 0);
    fc_issueH(sm, 1, 1);
    for (int c = 0; c < 32; c++) {
        if (c < 31) cp_wait<1>(); else cp_wait<0>();
        __syncthreads();
        if (c + 2 < 32) fc_issueH(sm, c + 2, (c + 2) % 3);
        __half* Hs = (__half*)(sm + OFF_DYN + (c % 3) * F_STG_B);
        #pragma unroll
        for (int kt = 0; kt < 2; kt++) {
            const int kk = c * 32 + kt * 16;
            wmma::fragment<wmma::matrix_a, 16, 16, 16, __half, wmma::row_major> a[2];
            wmma::fragment<wmma::matrix_b, 16, 16, 16, __half, wmma::col_major> b[2];
            wmma::load_matrix_sync(a[0], Hs + (mh * 2 + 0) * 16 * HLD2 + kt * 16, HLD2);
            wmma::load_matrix_sync(a[1], Hs + (mh * 2 + 1) * 16 * HLD2 + kt * 16, HLD2);
            wmma::load_matrix_sync(b[0], Wb + kk, HID);
            wmma::load_matrix_sync(b[1], Wb + (size_t)16 * HID + kk, HID);
            #pragma unroll
            for (int mt = 0; mt < 2; mt++)
                #pragma unroll
                for (int nt = 0; nt < 2; nt++)
                    wmma::mma_sync(acc[mt][nt], a[mt], b[nt], acc[mt][nt]);
        }
    }
    __syncthreads();   // stages free -> patch + rowmax

    float* patch = (float*)(sm + OFF_DYN) + warp * 16 * PLD;
    unsigned* srm = (unsigned*)((float*)(sm + OFF_DYN) + 16 * 16 * PLD);
    if (tid < 64) srm[tid] = 0u;
    __syncthreads();

    #pragma unroll
    for (int mt = 0; mt < 2; mt++) {
        #pragma unroll
        for (int nt = 0; nt < 2; nt++) {
            wmma::store_matrix_sync(patch, acc[mt][nt], PLD, wmma::mem_row_major);
            __syncwarp();
            const int col0 = cta * 256 + n8 * 32 + nt * 16;
            const int m0 = (mh * 2 + mt) * 16;
            #pragma unroll
            for (int e8 = 0; e8 < 8; e8++) {
                int e = lane + e8 * 32;
                int r = e >> 4, cc = e & 15;
                float val = patch[r * PLD + cc] + fcb[col0 + cc];
                out[((size_t)t * 64 + m0 + r) * VOC + col0 + cc] = val;
                float v = val;
                #pragma unroll
                for (int o = 8; o > 0; o >>= 1)
                    v = fmaxf(v, __shfl_xor_sync(0xffffffffu, v, o));
                if ((lane & 15) == 0) atomicMax(&srm[m0 + r], fenc(v));
            }
            __syncwarp();
        }
    }
    __syncthreads();
    if (tid < 64) g_pmax[cta * 64 + tid] = srm[tid];
}

// ---------------- argmax + x staging (start of next lstm phase, CTAs<64) ----------------
__device__ __forceinline__ void argmax_stage(char* sm, int t, int q, int hp,
        const float* fcW, const float* fcb, const float* dec_emb,
        const float* __restrict__ out) {
    const int cta = blockIdx.x, tid = threadIdx.x;
    const int row = cta;

    unsigned* spm  = (unsigned*)(sm + OFF_DYN);          // 128
    unsigned* sgm  = spm + 128;
    int* snc   = (int*)(sgm + 1);
    int* scnt  = snc + 1;
    int* stok  = scnt + 1;
    int* secta = stok + 1;                               // 128
    int* cand  = secta + 128;                            // 512

    if (tid < 128) spm[tid] = __ldcg(&g_pmax[tid * 64 + row]);
    if (tid == 0) { *snc = 0; *scnt = 0; }
    __syncthreads();
    if (tid < 32) {
        unsigned k = spm[tid];
        k = max(k, spm[tid + 32]);
        k = max(k, spm[tid + 64]);
        k = max(k, spm[tid + 96]);
        #pragma unroll
        for (int o = 16; o > 0; o >>= 1)
            k = max(k, __shfl_xor_sync(0xffffffffu, k, o));
        if (tid == 0) *sgm = k;
    }
    __syncthreads();
    const float th = fdec(*sgm) - 0.02f;

    if (tid < 128 && fdec(spm[tid]) >= th) {
        int e = atomicAdd(snc, 1);
        secta[e] = tid;
    }
    __syncthreads();
    int ne = *snc;

    const float* lg = out + ((size_t)t * 64 + row) * VOC;
    for (int e = 0; e < ne; e += 2) {
        int idx = e + (tid >> 8);
        if (idx < ne) {
            int c = secta[idx];
            int col = c * 256 + (tid & 255);
            float x = __ldcg(lg + col);
            if (x >= th) {
                int pp = atomicAdd(scnt, 1);
                if (pp < 512) cand[pp] = col;
            }
        }
    }
    __syncthreads();
    int n = *scnt; if (n > 512) n = 512;

    if (tid < 32) {
        const float* hr = g_h[hp] + row * HID;
        float bestv = -3.4e38f; int besti = 0x7fffffff;
        for (int ci = 0; ci < n; ci++) {
            int v = cand[ci];
            const float* wr = fcW + (size_t)v * HID;
            float s = 0.f;
            for (int k = tid; k < HID; k += 32) s += __ldcg(hr + k) * wr[k];
            #pragma unroll
            for (int o = 16; o > 0; o >>= 1) s += __shfl_xor_sync(0xffffffffu, s, o);
            s += fcb[v];
            if (s > bestv || (s == bestv && v < besti)) { bestv = s; besti = v; }
        }
        if (tid == 0) *stok = besti;
    }
    __syncthreads();
    int tok = *stok;
    __nv_bfloat16* oAh = g_A_hi[q];
    __nv_bfloat16* oAl = g_A_lo[q];
    for (int k = tid; k < EMB; k += NTHR) {
        float v = dec_emb[(size_t)tok * EMB + k];
        __nv_bfloat16 hi = __float2bfloat16(v);
        oAh[cta * KC + k] = hi;
        oAl[cta * KC + k] = __float2bfloat16(v - __bfloat162float(hi));
    }
    __threadfence();
    __syncthreads();
    if (tid == 0) red_add_rel(&g_xcnt, 1u);
    __syncthreads();
}

// ---------------- persistent kernel ----------------
__global__ void __launch_bounds__(NTHR, 1) persist(
        const int* __restrict__ src, const int* __restrict__ trg,
        const float* __restrict__ enc_emb, const float* __restrict__ dec_emb,
        const float* __restrict__ fcW, const float* __restrict__ fcb,
        float* __restrict__ out) {
    extern __shared__ char sm[];
    const int tid = threadIdx.x, cta = blockIdx.x;
    float* sC = (float*)(sm + OFF_C);
    unsigned gen = 0;

    sC[tid] = 0.f;

    load_weights_dev(sm, 0);

    if (cta < 64) {
        int tok = src[cta];
        for (int k = tid; k < EMB; k += NTHR) {
            float v = enc_emb[(size_t)tok * EMB + k];
            __nv_bfloat16 hi = __float2bfloat16(v);
            g_A_hi[0][cta * KC + k] = hi;
            g_A_lo[0][cta * KC + k] = __float2bfloat16(v - __bfloat162float(hi));
        }
    }
    gbar(++gen);

    // ---- encoder ----
    for (int s = 0; s < SRCLEN; s++) {
        int ntok = -1;
        const float* nemb = enc_emb;
        if (cta < 64) {
            if (s < SRCLEN - 1) { ntok = src[(s + 1) * BATCH + cta]; nemb = enc_emb; }
            else                { ntok = trg[cta];                   nemb = dec_emb; }
        }
        lstm_step_dev(sm, s & 1, 0, ntok, nemb, 0);
        gbar(++gen);
    }

    load_weights_dev(sm, 1);

    // ---- decoder: per step = [argmax(prev) + lstm] bar [fc] bar ----
    for (int d = 0; d < TRGLEN - 1; d++) {
        int p = d & 1;                 // (SRCLEN + d) & 1, SRCLEN even
        if (d > 0 && cta < 64)
            argmax_stage(sm, d, p, p, fcW, fcb, dec_emb, out);
        lstm_step_dev(sm, p, 1, -1, dec_emb, d);
        gbar(++gen);
        fc_step_dev(sm, d + 1, fcb, out);
        gbar(++gen);
    }
}

// ---------------- launch ----------------
extern "C" void kernel_launch(void* const* d_in, const int* in_sizes, int n_in,
                              void* d_out, int out_size) {
    const int*   src     = (const int*)  d_in[0];
    const int*   trg     = (const int*)  d_in[1];
    const float* enc_emb = (const float*)d_in[2];
    const float* eWih    = (const float*)d_in[3];
    const float* eWhh    = (const float*)d_in[4];
    const float* ebih    = (const float*)d_in[5];
    const float* ebhh    = (const float*)d_in[6];
    const float* dec_emb = (const float*)d_in[7];
    const float* dWih    = (const float*)d_in[8];
    const float* dWhh    = (const float*)d_in[9];
    const float* dbih    = (const float*)d_in[10];
    const float* dbhh    = (const float*)d_in[11];
    const float* fcW     = (const float*)d_in[12];
    const float* fcb     = (const float*)d_in[13];
    float* out = (float*)d_out;

    prep_fc<<<2048, 256>>>(fcW);
    prep_lstm<<<2048, 256>>>(eWih, eWhh, ebih, ebhh, dWih, dWhh, dbih, dbhh);
    init_k<<<2048, 256>>>(out);

    cudaFuncSetAttribute(persist, cudaFuncAttributeMaxDynamicSharedMemorySize, SMEM_TOTAL);
    persist<<<NCTA, NTHR, SMEM_TOTAL>>>(src, trg, enc_emb, dec_emb, fcW, fcb, out);
}

// round 16
// speedup vs baseline: 1.3505x; 1.3505x over previous
#include <cuda_runtime.h>
#include <cuda_fp16.h>
#include <cuda_bf16.h>
#include <mma.h>
#include <math.h>

using namespace nvcuda;

#define BATCH 64
#define HID   1024
#define EMB   256
#define VOC   32000
#define G4    4096
#define KC    1280
#define SRCLEN 64
#define TRGLEN 64
#define NCTA  128
#define NTHR  512

#define WLD   1288
#define ALD2  40        // LSTM 32-K chunk ld (bf16)
#define HLD   24        // fc h chunk ld (fp16)
#define BLD   24        // fc B tile ld (fp16)
#define SGLD  36
#define PLD   20

#define OFF_W    0
#define SZ_W     (2*32*WLD*2)            // 164,864
#define OFF_DYN  SZ_W
#define L_STG_B  (2*2*64*ALD2*2)         // 20,480 per LSTM stage (3 stages)
#define F_STG_B  (64*HLD*2 + 16*16*BLD*2) // 15,360 per fc stage (4 stages)
#define DYN_SZ   61440
#define OFF_C    (OFF_DYN + DYN_SZ)      // 226,304
#define SMEM_TOTAL (OFF_C + 2048)        // 228,352

// ---------------- device scratch ----------------
__device__ __align__(16) __half        g_W16[(size_t)VOC * HID];
__device__ __align__(16) __nv_bfloat16 g_Wl_hi[2 * (size_t)G4 * KC];
__device__ __align__(16) __nv_bfloat16 g_Wl_lo[2 * (size_t)G4 * KC];
__device__ __align__(16) float         g_bias[2 * G4];
__device__ __align__(16) float         g_h[BATCH * HID];
__device__ __align__(16) __half        g_h16[BATCH * HID];
__device__ __align__(16) __nv_bfloat16 g_A_hi[2][BATCH * KC];
__device__ __align__(16) __nv_bfloat16 g_A_lo[2][BATCH * KC];
__device__ unsigned g_pmax[NCTA * BATCH];
__device__ unsigned g_bcount;            // single-counter grid barrier

// ---------------- helpers ----------------
__device__ __forceinline__ void cpa16(void* dst, const void* src) {
    unsigned d = (unsigned)__cvta_generic_to_shared(dst);
    asm volatile("cp.async.cg.shared.global [%0], [%1], 16;\n" :: "r"(d), "l"(src));
}
__device__ __forceinline__ void cp_commit() { asm volatile("cp.async.commit_group;\n"); }
template<int N> __device__ __forceinline__ void cp_wait() {
    asm volatile("cp.async.wait_group %0;\n" :: "n"(N));
}
__device__ __forceinline__ unsigned fenc(float f) {
    unsigned u = __float_as_uint(f);
    return (u & 0x80000000u) ? ~u : (u | 0x80000000u);
}
__device__ __forceinline__ float fdec(unsigned k) {
    return (k & 0x80000000u) ? __uint_as_float(k & 0x7fffffffu) : __uint_as_float(~k);
}
__device__ __forceinline__ unsigned ld_acq(const unsigned* p) {
    unsigned v;
    asm volatile("ld.acquire.gpu.global.u32 %0, [%1];" : "=r"(v) : "l"(p));
    return v;
}
__device__ __forceinline__ void red_add_rel(unsigned* p, unsigned v) {
    asm volatile("red.add.release.gpu.global.u32 [%0], %1;" :: "l"(p), "r"(v));
}
// counter barrier: 1 release-add per CTA, 1 poller thread per CTA on one line
__device__ __forceinline__ void gbar(unsigned gen) {
    __syncthreads();
    if (threadIdx.x == 0) {
        red_add_rel(&g_bcount, 1u);
        while (ld_acq(&g_bcount) < (unsigned)NCTA * gen) { }
    }
    __syncthreads();
}

// ---------------- prep kernels ----------------
__global__ void prep_fc(const float* __restrict__ W) {
    size_t stride = (size_t)gridDim.x * blockDim.x;
    for (size_t i = (size_t)blockIdx.x * blockDim.x + threadIdx.x;
         i < (size_t)VOC * HID; i += stride)
        g_W16[i] = __float2half(W[i]);
}

__global__ void prep_lstm(const float* __restrict__ eWih, const float* __restrict__ eWhh,
                          const float* __restrict__ ebih, const float* __restrict__ ebhh,
                          const float* __restrict__ dWih, const float* __restrict__ dWhh,
                          const float* __restrict__ dbih, const float* __restrict__ dbhh) {
    size_t stride = (size_t)gridDim.x * blockDim.x;
    size_t gid0 = (size_t)blockIdx.x * blockDim.x + threadIdx.x;
    const size_t per = (size_t)G4 * KC;
    for (size_t i = gid0; i < 2 * per; i += stride) {
        int sel = (int)(i / per);
        size_t rem = i - (size_t)sel * per;
        int r = (int)(rem / KC);
        int k = (int)(rem % KC);
        int j = r >> 2, gate = r & 3;
        int orow = gate * HID + j;
        const float* Wih = sel ? dWih : eWih;
        const float* Whh = sel ? dWhh : eWhh;
        float v = (k < EMB) ? Wih[(size_t)orow * EMB + k]
                            : Whh[(size_t)orow * HID + (k - EMB)];
        __nv_bfloat16 hi = __float2bfloat16(v);
        g_Wl_hi[i] = hi;
        g_Wl_lo[i] = __float2bfloat16(v - __bfloat162float(hi));
    }
    for (size_t i = gid0; i < 2 * G4; i += stride) {
        int sel = (int)(i / G4);
        int r = (int)(i % G4);
        int j = r >> 2, gate = r & 3;
        int orow = gate * HID + j;
        g_bias[i] = sel ? (dbih[orow] + dbhh[orow]) : (ebih[orow] + ebhh[orow]);
    }
}

__global__ void init_k(float* __restrict__ out) {
    size_t stride = (size_t)gridDim.x * blockDim.x;
    size_t g0 = (size_t)blockIdx.x * blockDim.x + threadIdx.x;
    for (size_t i = g0; i < (size_t)BATCH * VOC; i += stride) out[i] = 0.f;
    for (size_t i = g0; i < (size_t)64 * 1024; i += stride) {
        int b = (int)(i >> 10), j = (int)(i & 1023);
        g_A_hi[0][b * KC + EMB + j] = __float2bfloat16(0.f);
        g_A_lo[0][b * KC + EMB + j] = __float2bfloat16(0.f);
    }
    if (g0 == 0) g_bcount = 0u;
}

// ---------------- weight load into smem ----------------
__device__ __forceinline__ void load_weights_dev(char* sm, int sel) {
    const int tid = threadIdx.x, cta = blockIdx.x;
    __nv_bfloat16* sWhi = (__nv_bfloat16*)(sm + OFF_W);
    __nv_bfloat16* sWlo = sWhi + 32 * WLD;
    const __nv_bfloat16* gh = g_Wl_hi + (size_t)sel * G4 * KC + (size_t)cta * 32 * KC;
    const __nv_bfloat16* gl = g_Wl_lo + (size_t)sel * G4 * KC + (size_t)cta * 32 * KC;
    for (int o = tid; o < 32 * 160; o += NTHR) {
        int r = o / 160, g = o % 160;
        *(float4*)(sWhi + r * WLD + g * 8) = *(const float4*)(gh + (size_t)r * KC + g * 8);
        *(float4*)(sWlo + r * WLD + g * 8) = *(const float4*)(gl + (size_t)r * KC + g * 8);
    }
    __syncthreads();
}

// ---------------- LSTM phase ----------------
// stage layout (bf16 elems): [ks(2)][mat(2)][r(64)][ALD2]; ks stride 5120, mat stride 2560
__device__ __forceinline__ void lstm_issue(char* sm, const __nv_bfloat16* gAh,
                                           const __nv_bfloat16* gAl, int c, int st) {
    __nv_bfloat16* base = (__nv_bfloat16*)(sm + OFF_DYN + st * L_STG_B);
    const int tid = threadIdx.x;
    #pragma unroll
    for (int j = 0; j < 2; j++) {
        int o = tid + j * NTHR;
        int ks = o >> 9;
        int rem = o & 511;
        int mat = rem >> 8;
        int rem2 = rem & 255;
        int r = rem2 >> 2, kg = rem2 & 3;
        int k0 = ks * 640 + c * 32;
        const __nv_bfloat16* src = (mat ? gAl : gAh) + (size_t)r * KC + k0 + kg * 8;
        cpa16(base + ks * 5120 + mat * 2560 + r * ALD2 + kg * 8, src);
    }
    cp_commit();
}

__device__ __forceinline__ void lstm_step_dev(char* sm, int p, int sel,
                                              int nx_tok, const float* nx_emb) {
    const int tid = threadIdx.x, cta = blockIdx.x;
    const int warp = tid >> 5;
    const int mw = warp & 3, cw = (warp >> 2) & 1, ks = warp >> 3;
    __nv_bfloat16* sWhi = (__nv_bfloat16*)(sm + OFF_W);
    __nv_bfloat16* sWlo = sWhi + 32 * WLD;
    float* sC = (float*)(sm + OFF_C);

    const __nv_bfloat16* gAh = g_A_hi[p];
    const __nv_bfloat16* gAl = g_A_lo[p];

    wmma::fragment<wmma::accumulator, 16, 16, 16, float> a_hh, a_hl, a_lh;
    wmma::fill_fragment(a_hh, 0.f);
    wmma::fill_fragment(a_hl, 0.f);
    wmma::fill_fragment(a_lh, 0.f);

    lstm_issue(sm, gAh, gAl, 0, 0);
    lstm_issue(sm, gAh, gAl, 1, 1);
    for (int c = 0; c < 20; c++) {
        if (c < 19) cp_wait<1>(); else cp_wait<0>();
        __syncthreads();
        if (c + 2 < 20) lstm_issue(sm, gAh, gAl, c + 2, (c + 2) % 3);
        const __nv_bfloat16* Ahi =
            (const __nv_bfloat16*)(sm + OFF_DYN + (c % 3) * L_STG_B) + ks * 5120 + mw * 16 * ALD2;
        const __nv_bfloat16* Alo = Ahi + 2560;
        #pragma unroll
        for (int ktl = 0; ktl < 2; ktl++) {
            wmma::fragment<wmma::matrix_a, 16, 16, 16, __nv_bfloat16, wmma::row_major> ahi, alo;
            wmma::fragment<wmma::matrix_b, 16, 16, 16, __nv_bfloat16, wmma::col_major> bhi, blo;
            wmma::load_matrix_sync(ahi, Ahi + ktl * 16, ALD2);
            wmma::load_matrix_sync(alo, Alo + ktl * 16, ALD2);
            int kk = ks * 640 + c * 32 + ktl * 16;
            wmma::load_matrix_sync(bhi, sWhi + cw * 16 * WLD + kk, WLD);
            wmma::load_matrix_sync(blo, sWlo + cw * 16 * WLD + kk, WLD);
            wmma::mma_sync(a_hh, ahi, bhi, a_hh);
            wmma::mma_sync(a_hl, ahi, blo, a_hl);
            wmma::mma_sync(a_lh, alo, bhi, a_lh);
        }
    }
    #pragma unroll
    for (int i = 0; i < a_hh.num_elements; i++)
        a_hh.x[i] += a_hl.x[i] + a_lh.x[i];

    __syncthreads();
    float* sgP = (float*)(sm + OFF_DYN) + ks * (64 * SGLD);
    wmma::store_matrix_sync(sgP + mw * 16 * SGLD + cw * 16, a_hh, SGLD, wmma::mem_row_major);
    __syncthreads();

    const float* bias = g_bias + sel * G4 + cta * 32;
    float* sg0 = (float*)(sm + OFF_DYN);
    float* sg1 = sg0 + 64 * SGLD;
    int q = p ^ 1;
    __nv_bfloat16* oAh = g_A_hi[q];
    __nv_bfloat16* oAl = g_A_lo[q];
    {
        int e = tid;                       // 512 = 64 rows x 8 h-units
        int b = e >> 3, jj = e & 7;
        float gi = sg0[b * SGLD + jj * 4 + 0] + sg1[b * SGLD + jj * 4 + 0] + bias[jj * 4 + 0];
        float gf = sg0[b * SGLD + jj * 4 + 1] + sg1[b * SGLD + jj * 4 + 1] + bias[jj * 4 + 1];
        float gg = sg0[b * SGLD + jj * 4 + 2] + sg1[b * SGLD + jj * 4 + 2] + bias[jj * 4 + 2];
        float go = sg0[b * SGLD + jj * 4 + 3] + sg1[b * SGLD + jj * 4 + 3] + bias[jj * 4 + 3];
        float cold = sC[e];
        float si = 1.f / (1.f + expf(-gi));
        float sf = 1.f / (1.f + expf(-gf));
        float so = 1.f / (1.f + expf(-go));
        float cn = sf * cold + si * tanhf(gg);
        float hn = so * tanhf(cn);
        sC[e] = cn;
        int j = cta * 8 + jj;
        g_h[b * HID + j] = hn;
        g_h16[b * HID + j] = __float2half(hn);
        __nv_bfloat16 hi = __float2bfloat16(hn);
        oAh[b * KC + EMB + j] = hi;
        oAl[b * KC + EMB + j] = __float2bfloat16(hn - __bfloat162float(hi));
    }
    if (nx_tok >= 0 && cta < 64) {
        for (int k = tid; k < EMB; k += NTHR) {
            float v = nx_emb[(size_t)nx_tok * EMB + k];
            __nv_bfloat16 hi = __float2bfloat16(v);
            oAh[cta * KC + k] = hi;
            oAl[cta * KC + k] = __float2bfloat16(v - __bfloat162float(hi));
        }
    }
}

// ---------------- fc phase: CTA = 256 contiguous cols, warp = 1 tile ----------------
__device__ __forceinline__ void fc_issue(char* sm, int c, int st, int tile) {
    const int tid = threadIdx.x, warp = tid >> 5, lane = tid & 31;
    __half* Hs = (__half*)(sm + OFF_DYN + st * F_STG_B);
    __half* Bw = Hs + 64 * HLD + warp * (16 * BLD);
    const int k0 = c * 16;
    if (tid < 128) {
        int r = tid >> 1, g = tid & 1;
        cpa16(Hs + r * HLD + g * 8, g_h16 + r * HID + k0 + g * 8);
    }
    {
        int cc = lane >> 1, g = lane & 1;
        cpa16(Bw + cc * BLD + g * 8,
              g_W16 + (size_t)(tile * 16 + cc) * HID + k0 + g * 8);
    }
    cp_commit();
}

__device__ __forceinline__ void fc_step_dev(char* sm, int t, const float* fcb,
                                            float* __restrict__ out) {
    const int tid = threadIdx.x, cta = blockIdx.x;
    const int warp = tid >> 5, lane = tid & 31;

    if (cta >= 125) {
        if (tid < 64) g_pmax[cta * 64 + tid] = 0u;
        return;
    }
    const int tile = cta * 16 + warp;

    wmma::fragment<wmma::accumulator, 16, 16, 16, float> acc[4];
    #pragma unroll
    for (int m = 0; m < 4; m++) wmma::fill_fragment(acc[m], 0.f);

    fc_issue(sm, 0, 0, tile);
    fc_issue(sm, 1, 1, tile);
    fc_issue(sm, 2, 2, tile);
    for (int c = 0; c < 64; c++) {
        if (c < 62) cp_wait<2>();
        else if (c == 62) cp_wait<1>();
        else cp_wait<0>();
        __syncthreads();
        if (c + 3 < 64) fc_issue(sm, c + 3, (c + 3) & 3, tile);
        __half* Hs = (__half*)(sm + OFF_DYN + (c & 3) * F_STG_B);
        __half* Bw = Hs + 64 * HLD + warp * (16 * BLD);
        wmma::fragment<wmma::matrix_b, 16, 16, 16, __half, wmma::col_major> b0;
        wmma::load_matrix_sync(b0, Bw, BLD);
        #pragma unroll
        for (int m = 0; m < 4; m++) {
            wmma::fragment<wmma::matrix_a, 16, 16, 16, __half, wmma::row_major> a;
            wmma::load_matrix_sync(a, Hs + m * 16 * HLD, HLD);
            wmma::mma_sync(acc[m], a, b0, acc[m]);
        }
    }
    __syncthreads();   // stages free -> patch + rowmax

    float* patch = (float*)(sm + OFF_DYN) + warp * 16 * PLD;
    unsigned* srm = (unsigned*)((float*)(sm + OFF_DYN) + 16 * 16 * PLD);
    if (tid < 64) srm[tid] = 0u;
    __syncthreads();

    const int col0 = tile * 16;
    #pragma unroll
    for (int m = 0; m < 4; m++) {
        wmma::store_matrix_sync(patch, acc[m], PLD, wmma::mem_row_major);
        __syncwarp();
        #pragma unroll
        for (int e8 = 0; e8 < 8; e8++) {
            int e = lane + e8 * 32;
            int r = e >> 4, cc = e & 15;
            float val = patch[r * PLD + cc] + fcb[col0 + cc];
            out[((size_t)t * 64 + m * 16 + r) * VOC + col0 + cc] = val;
            float v = val;
            #pragma unroll
            for (int o = 8; o > 0; o >>= 1)
                v = fmaxf(v, __shfl_xor_sync(0xffffffffu, v, o));
            if ((lane & 15) == 0) atomicMax(&srm[m * 16 + r], fenc(v));
        }
        __syncwarp();
    }
    __syncthreads();
    if (tid < 64) g_pmax[cta * 64 + tid] = srm[tid];
}

// ---------------- argmax phase (separate, CTAs<64) ----------------
__device__ __forceinline__ void argmax_dev(char* sm, int t, int q,
        const float* fcW, const float* fcb, const float* dec_emb,
        const float* __restrict__ out) {
    const int cta = blockIdx.x, tid = threadIdx.x;
    if (cta >= 64) return;
    const int row = cta;

    unsigned* spm  = (unsigned*)(sm + OFF_DYN);          // 128
    unsigned* sgm  = spm + 128;
    int* snc   = (int*)(sgm + 1);
    int* scnt  = snc + 1;
    int* stok  = scnt + 1;
    int* secta = stok + 1;                               // 128
    int* cand  = secta + 128;                            // 512

    if (tid < 128) spm[tid] = __ldcg(&g_pmax[tid * 64 + row]);
    if (tid == 0) { *snc = 0; *scnt = 0; }
    __syncthreads();
    if (tid < 32) {
        unsigned k = spm[tid];
        k = max(k, spm[tid + 32]);
        k = max(k, spm[tid + 64]);
        k = max(k, spm[tid + 96]);
        #pragma unroll
        for (int o = 16; o > 0; o >>= 1)
            k = max(k, __shfl_xor_sync(0xffffffffu, k, o));
        if (tid == 0) *sgm = k;
    }
    __syncthreads();
    const float th = fdec(*sgm) - 0.02f;

    if (tid < 128 && fdec(spm[tid]) >= th) {
        int e = atomicAdd(snc, 1);
        secta[e] = tid;
    }
    __syncthreads();
    int ne = *snc;

    const float* lg = out + ((size_t)t * 64 + row) * VOC;
    for (int e = 0; e < ne; e += 2) {
        int idx = e + (tid >> 8);
        if (idx < ne) {
            int c = secta[idx];
            int col = c * 256 + (tid & 255);
            float x = __ldcg(lg + col);
            if (x >= th) {
                int pp = atomicAdd(scnt, 1);
                if (pp < 512) cand[pp] = col;
            }
        }
    }
    __syncthreads();
    int n = *scnt; if (n > 512) n = 512;

    if (tid < 32) {
        const float* hr = g_h + row * HID;
        float bestv = -3.4e38f; int besti = 0x7fffffff;
        for (int ci = 0; ci < n; ci++) {
            int v = cand[ci];
            const float* wr = fcW + (size_t)v * HID;
            float s = 0.f;
            for (int k = tid; k < HID; k += 32) s += __ldcg(hr + k) * wr[k];
            #pragma unroll
            for (int o = 16; o > 0; o >>= 1) s += __shfl_xor_sync(0xffffffffu, s, o);
            s += fcb[v];
            if (s > bestv || (s == bestv && v < besti)) { bestv = s; besti = v; }
        }
        if (tid == 0) *stok = besti;
    }
    __syncthreads();
    int tok = *stok;
    __nv_bfloat16* oAh = g_A_hi[q];
    __nv_bfloat16* oAl = g_A_lo[q];
    for (int k = tid; k < EMB; k += NTHR) {
        float v = dec_emb[(size_t)tok * EMB + k];
        __nv_bfloat16 hi = __float2bfloat16(v);
        oAh[cta * KC + k] = hi;
        oAl[cta * KC + k] = __float2bfloat16(v - __bfloat162float(hi));
    }
}

// ---------------- persistent kernel ----------------
__global__ void __launch_bounds__(NTHR, 1) persist(
        const int* __restrict__ src, const int* __restrict__ trg,
        const float* __restrict__ enc_emb, const float* __restrict__ dec_emb,
        const float* __restrict__ fcW, const float* __restrict__ fcb,
        float* __restrict__ out) {
    extern __shared__ char sm[];
    const int tid = threadIdx.x, cta = blockIdx.x;
    float* sC = (float*)(sm + OFF_C);
    unsigned gen = 0;

    sC[tid] = 0.f;

    load_weights_dev(sm, 0);

    if (cta < 64) {
        int tok = src[cta];
        for (int k = tid; k < EMB; k += NTHR) {
            float v = enc_emb[(size_t)tok * EMB + k];
            __nv_bfloat16 hi = __float2bfloat16(v);
            g_A_hi[0][cta * KC + k] = hi;
            g_A_lo[0][cta * KC + k] = __float2bfloat16(v - __bfloat162float(hi));
        }
    }
    gbar(++gen);

    // ---- encoder ----
    for (int s = 0; s < SRCLEN; s++) {
        int ntok = -1;
        const float* nemb = enc_emb;
        if (cta < 64) {
            if (s < SRCLEN - 1) { ntok = src[(s + 1) * BATCH + cta]; nemb = enc_emb; }
            else                { ntok = trg[cta];                   nemb = dec_emb; }
        }
        lstm_step_dev(sm, s & 1, 0, ntok, nemb);
        gbar(++gen);
    }

    load_weights_dev(sm, 1);

    // ---- decoder: per step = [lstm] bar [fc] bar [argmax] bar ----
    for (int d = 0; d < TRGLEN - 1; d++) {
        int p = d & 1;                 // (SRCLEN + d) & 1, SRCLEN even
        lstm_step_dev(sm, p, 1, -1, dec_emb);
        gbar(++gen);
        fc_step_dev(sm, d + 1, fcb, out);
        gbar(++gen);
        argmax_dev(sm, d + 1, p ^ 1, fcW, fcb, dec_emb, out);
        gbar(++gen);
    }
}

// ---------------- launch ----------------
extern "C" void kernel_launch(void* const* d_in, const int* in_sizes, int n_in,
                              void* d_out, int out_size) {
    const int*   src     = (const int*)  d_in[0];
    const int*   trg     = (const int*)  d_in[1];
    const float* enc_emb = (const float*)d_in[2];
    const float* eWih    = (const float*)d_in[3];
    const float* eWhh    = (const float*)d_in[4];
    const float* ebih    = (const float*)d_in[5];
    const float* ebhh    = (const float*)d_in[6];
    const float* dec_emb = (const float*)d_in[7];
    const float* dWih    = (const float*)d_in[8];
    const float* dWhh    = (const float*)d_in[9];
    const float* dbih    = (const float*)d_in[10];
    const float* dbhh    = (const float*)d_in[11];
    const float* fcW     = (const float*)d_in[12];
    const float* fcb     = (const float*)d_in[13];
    float* out = (float*)d_out;

    prep_fc<<<2048, 256>>>(fcW);
    prep_lstm<<<2048, 256>>>(eWih, eWhh, ebih, ebhh, dWih, dWhh, dbih, dbhh);
    init_k<<<2048, 256>>>(out);

    cudaFuncSetAttribute(persist, cudaFuncAttributeMaxDynamicSharedMemorySize, SMEM_TOTAL);
    persist<<<NCTA, NTHR, SMEM_TOTAL>>>(src, trg, enc_emb, dec_emb, fcW, fcb, out);
}

// round 17
// speedup vs baseline: 1.3562x; 1.0042x over previous
#include <cuda_runtime.h>
#include <cuda_fp16.h>
#include <cuda_bf16.h>
#include <mma.h>
#include <math.h>

using namespace nvcuda;

#define BATCH 64
#define HID   1024
#define EMB   256
#define VOC   32000
#define G4    4096
#define KC    1280
#define SRCLEN 64
#define TRGLEN 64
#define NCTA  128
#define NTHR  512

#define WLD   1288
#define ALD2  40        // LSTM 32-K chunk ld (bf16)
#define HLD   24        // fc h chunk ld (fp16)
#define BLD   24        // fc B tile ld (fp16)
#define SGLD  36
#define PLD   20

#define OFF_W    0
#define SZ_W     (2*32*WLD*2)            // 164,864
#define OFF_DYN  SZ_W
#define L_STG_B  (2*2*64*ALD2*2)         // 20,480 per LSTM stage (3 stages)
#define F_STG_B  (64*HLD*2 + 16*16*BLD*2) // 15,360 per fc stage (4 stages)
#define DYN_SZ   61440
#define OFF_C    (OFF_DYN + DYN_SZ)      // 226,304
#define SMEM_TOTAL (OFF_C + 2048)        // 228,352

// LSTM position->chunk order: h chunks (8..19) first, x chunks (0..7) last
#define ORD(i) (((i) < 12) ? ((i) + 8) : ((i) - 12))

// ---------------- device scratch ----------------
__device__ __align__(16) __half        g_W16[(size_t)VOC * HID];
__device__ __align__(16) __nv_bfloat16 g_Wl_hi[2 * (size_t)G4 * KC];
__device__ __align__(16) __nv_bfloat16 g_Wl_lo[2 * (size_t)G4 * KC];
__device__ __align__(16) float         g_bias[2 * G4];
__device__ __align__(16) float         g_h[2][BATCH * HID];   // parity-buffered fp32 h
__device__ __align__(16) __half        g_h16[BATCH * HID];
__device__ __align__(16) __nv_bfloat16 g_A_hi[2][BATCH * KC];
__device__ __align__(16) __nv_bfloat16 g_A_lo[2][BATCH * KC];
__device__ unsigned g_pmax[NCTA * BATCH];
__device__ unsigned g_bcount;            // single-counter grid barrier
__device__ unsigned g_xcnt;              // decoder x-staging counter (64 per step)

// ---------------- helpers ----------------
__device__ __forceinline__ void cpa16(void* dst, const void* src) {
    unsigned d = (unsigned)__cvta_generic_to_shared(dst);
    asm volatile("cp.async.cg.shared.global [%0], [%1], 16;\n" :: "r"(d), "l"(src));
}
__device__ __forceinline__ void cp_commit() { asm volatile("cp.async.commit_group;\n"); }
template<int N> __device__ __forceinline__ void cp_wait() {
    asm volatile("cp.async.wait_group %0;\n" :: "n"(N));
}
__device__ __forceinline__ unsigned fenc(float f) {
    unsigned u = __float_as_uint(f);
    return (u & 0x80000000u) ? ~u : (u | 0x80000000u);
}
__device__ __forceinline__ float fdec(unsigned k) {
    return (k & 0x80000000u) ? __uint_as_float(k & 0x7fffffffu) : __uint_as_float(~k);
}
__device__ __forceinline__ unsigned ld_acq(const unsigned* p) {
    unsigned v;
    asm volatile("ld.acquire.gpu.global.u32 %0, [%1];" : "=r"(v) : "l"(p));
    return v;
}
__device__ __forceinline__ void red_add_rel(unsigned* p, unsigned v) {
    asm volatile("red.add.release.gpu.global.u32 [%0], %1;" :: "l"(p), "r"(v));
}
// counter barrier: 1 release-add per CTA, 1 poller thread per CTA on one line
__device__ __forceinline__ void gbar(unsigned gen) {
    __syncthreads();
    if (threadIdx.x == 0) {
        red_add_rel(&g_bcount, 1u);
        while (ld_acq(&g_bcount) < (unsigned)NCTA * gen) { }
    }
    __syncthreads();
}

// ---------------- prep kernels ----------------
__global__ void prep_fc(const float* __restrict__ W) {
    size_t stride = (size_t)gridDim.x * blockDim.x;
    for (size_t i = (size_t)blockIdx.x * blockDim.x + threadIdx.x;
         i < (size_t)VOC * HID; i += stride)
        g_W16[i] = __float2half(W[i]);
}

__global__ void prep_lstm(const float* __restrict__ eWih, const float* __restrict__ eWhh,
                          const float* __restrict__ ebih, const float* __restrict__ ebhh,
                          const float* __restrict__ dWih, const float* __restrict__ dWhh,
                          const float* __restrict__ dbih, const float* __restrict__ dbhh) {
    size_t stride = (size_t)gridDim.x * blockDim.x;
    size_t gid0 = (size_t)blockIdx.x * blockDim.x + threadIdx.x;
    const size_t per = (size_t)G4 * KC;
    for (size_t i = gid0; i < 2 * per; i += stride) {
        int sel = (int)(i / per);
        size_t rem = i - (size_t)sel * per;
        int r = (int)(rem / KC);
        int k = (int)(rem % KC);
        int j = r >> 2, gate = r & 3;
        int orow = gate * HID + j;
        const float* Wih = sel ? dWih : eWih;
        const float* Whh = sel ? dWhh : eWhh;
        float v = (k < EMB) ? Wih[(size_t)orow * EMB + k]
                            : Whh[(size_t)orow * HID + (k - EMB)];
        __nv_bfloat16 hi = __float2bfloat16(v);
        g_Wl_hi[i] = hi;
        g_Wl_lo[i] = __float2bfloat16(v - __bfloat162float(hi));
    }
    for (size_t i = gid0; i < 2 * G4; i += stride) {
        int sel = (int)(i / G4);
        int r = (int)(i % G4);
        int j = r >> 2, gate = r & 3;
        int orow = gate * HID + j;
        g_bias[i] = sel ? (dbih[orow] + dbhh[orow]) : (ebih[orow] + ebhh[orow]);
    }
}

__global__ void init_k(float* __restrict__ out) {
    size_t stride = (size_t)gridDim.x * blockDim.x;
    size_t g0 = (size_t)blockIdx.x * blockDim.x + threadIdx.x;
    for (size_t i = g0; i < (size_t)BATCH * VOC; i += stride) out[i] = 0.f;
    for (size_t i = g0; i < (size_t)64 * 1024; i += stride) {
        int b = (int)(i >> 10), j = (int)(i & 1023);
        g_A_hi[0][b * KC + EMB + j] = __float2bfloat16(0.f);
        g_A_lo[0][b * KC + EMB + j] = __float2bfloat16(0.f);
    }
    if (g0 == 0) { g_bcount = 0u; g_xcnt = 0u; }
}

// ---------------- weight load into smem ----------------
__device__ __forceinline__ void load_weights_dev(char* sm, int sel) {
    const int tid = threadIdx.x, cta = blockIdx.x;
    __nv_bfloat16* sWhi = (__nv_bfloat16*)(sm + OFF_W);
    __nv_bfloat16* sWlo = sWhi + 32 * WLD;
    const __nv_bfloat16* gh = g_Wl_hi + (size_t)sel * G4 * KC + (size_t)cta * 32 * KC;
    const __nv_bfloat16* gl = g_Wl_lo + (size_t)sel * G4 * KC + (size_t)cta * 32 * KC;
    for (int o = tid; o < 32 * 160; o += NTHR) {
        int r = o / 160, g = o % 160;
        *(float4*)(sWhi + r * WLD + g * 8) = *(const float4*)(gh + (size_t)r * KC + g * 8);
        *(float4*)(sWlo + r * WLD + g * 8) = *(const float4*)(gl + (size_t)r * KC + g * 8);
    }
    __syncthreads();
}

// ---------------- LSTM phase ----------------
// stage layout (bf16 elems): [ks(2)][mat(2)][r(64)][ALD2]
__device__ __forceinline__ void lstm_issue(char* sm, const __nv_bfloat16* gAh,
                                           const __nv_bfloat16* gAl, int c, int st) {
    __nv_bfloat16* base = (__nv_bfloat16*)(sm + OFF_DYN + st * L_STG_B);
    const int tid = threadIdx.x;
    #pragma unroll
    for (int j = 0; j < 2; j++) {
        int o = tid + j * NTHR;
        int ks = o >> 9;
        int rem = o & 511;
        int mat = rem >> 8;
        int rem2 = rem & 255;
        int r = rem2 >> 2, kg = rem2 & 3;
        int k0 = ks * 640 + c * 32;
        const __nv_bfloat16* src = (mat ? gAl : gAh) + (size_t)r * KC + k0 + kg * 8;
        cpa16(base + ks * 5120 + mat * 2560 + r * ALD2 + kg * 8, src);
    }
    cp_commit();
}

__device__ __forceinline__ void lstm_step_dev(char* sm, int p, int sel,
                                              int nx_tok, const float* nx_emb,
                                              int xtag) {
    const int tid = threadIdx.x, cta = blockIdx.x;
    const int warp = tid >> 5;
    const int mw = warp & 3, cw = (warp >> 2) & 1, ks = warp >> 3;
    __nv_bfloat16* sWhi = (__nv_bfloat16*)(sm + OFF_W);
    __nv_bfloat16* sWlo = sWhi + 32 * WLD;
    float* sC = (float*)(sm + OFF_C);

    const __nv_bfloat16* gAh = g_A_hi[p];
    const __nv_bfloat16* gAl = g_A_lo[p];

    wmma::fragment<wmma::accumulator, 16, 16, 16, float> a_hh, a_hl, a_lh;
    wmma::fill_fragment(a_hh, 0.f);
    wmma::fill_fragment(a_hl, 0.f);
    wmma::fill_fragment(a_lh, 0.f);

    lstm_issue(sm, gAh, gAl, ORD(0), 0);
    lstm_issue(sm, gAh, gAl, ORD(1), 1);
    for (int c = 0; c < 20; c++) {
        if (c < 19) cp_wait<1>(); else cp_wait<0>();
        // gate before issuing first x-dependent chunk (ORD(12)=0 issued at c==10)
        if (xtag > 0 && c == 10) {
            if (tid == 0) {
                while (ld_acq(&g_xcnt) < (unsigned)(64 * xtag)) { }
            }
        }
        __syncthreads();
        if (c + 2 < 20) lstm_issue(sm, gAh, gAl, ORD(c + 2), (c + 2) % 3);
        const int oc = ORD(c);
        const __nv_bfloat16* Ahi =
            (const __nv_bfloat16*)(sm + OFF_DYN + (c % 3) * L_STG_B) + ks * 5120 + mw * 16 * ALD2;
        const __nv_bfloat16* Alo = Ahi + 2560;
        #pragma unroll
        for (int ktl = 0; ktl < 2; ktl++) {
            wmma::fragment<wmma::matrix_a, 16, 16, 16, __nv_bfloat16, wmma::row_major> ahi, alo;
            wmma::fragment<wmma::matrix_b, 16, 16, 16, __nv_bfloat16, wmma::col_major> bhi, blo;
            wmma::load_matrix_sync(ahi, Ahi + ktl * 16, ALD2);
            wmma::load_matrix_sync(alo, Alo + ktl * 16, ALD2);
            int kk = ks * 640 + oc * 32 + ktl * 16;
            wmma::load_matrix_sync(bhi, sWhi + cw * 16 * WLD + kk, WLD);
            wmma::load_matrix_sync(blo, sWlo + cw * 16 * WLD + kk, WLD);
            wmma::mma_sync(a_hh, ahi, bhi, a_hh);
            wmma::mma_sync(a_hl, ahi, blo, a_hl);
            wmma::mma_sync(a_lh, alo, bhi, a_lh);
        }
    }
    #pragma unroll
    for (int i = 0; i < a_hh.num_elements; i++)
        a_hh.x[i] += a_hl.x[i] + a_lh.x[i];

    __syncthreads();
    float* sgP = (float*)(sm + OFF_DYN) + ks * (64 * SGLD);
    wmma::store_matrix_sync(sgP + mw * 16 * SGLD + cw * 16, a_hh, SGLD, wmma::mem_row_major);
    __syncthreads();

    const float* bias = g_bias + sel * G4 + cta * 32;
    float* sg0 = (float*)(sm + OFF_DYN);
    float* sg1 = sg0 + 64 * SGLD;
    int q = p ^ 1;
    __nv_bfloat16* oAh = g_A_hi[q];
    __nv_bfloat16* oAl = g_A_lo[q];
    {
        int e = tid;                       // 512 = 64 rows x 8 h-units
        int b = e >> 3, jj = e & 7;
        float gi = sg0[b * SGLD + jj * 4 + 0] + sg1[b * SGLD + jj * 4 + 0] + bias[jj * 4 + 0];
        float gf = sg0[b * SGLD + jj * 4 + 1] + sg1[b * SGLD + jj * 4 + 1] + bias[jj * 4 + 1];
        float gg = sg0[b * SGLD + jj * 4 + 2] + sg1[b * SGLD + jj * 4 + 2] + bias[jj * 4 + 2];
        float go = sg0[b * SGLD + jj * 4 + 3] + sg1[b * SGLD + jj * 4 + 3] + bias[jj * 4 + 3];
        float cold = sC[e];
        float si = 1.f / (1.f + expf(-gi));
        float sf = 1.f / (1.f + expf(-gf));
        float so = 1.f / (1.f + expf(-go));
        float cn = sf * cold + si * tanhf(gg);
        float hn = so * tanhf(cn);
        sC[e] = cn;
        int j = cta * 8 + jj;
        g_h[q][b * HID + j] = hn;
        g_h16[b * HID + j] = __float2half(hn);
        __nv_bfloat16 hi = __float2bfloat16(hn);
        oAh[b * KC + EMB + j] = hi;
        oAl[b * KC + EMB + j] = __float2bfloat16(hn - __bfloat162float(hi));
    }
    if (nx_tok >= 0 && cta < 64) {
        for (int k = tid; k < EMB; k += NTHR) {
            float v = nx_emb[(size_t)nx_tok * EMB + k];
            __nv_bfloat16 hi = __float2bfloat16(v);
            oAh[cta * KC + k] = hi;
            oAl[cta * KC + k] = __float2bfloat16(v - __bfloat162float(hi));
        }
    }
}

// ---------------- fc phase: CTA = 256 contiguous cols, warp = 1 tile ----------------
__device__ __forceinline__ void fc_issue(char* sm, int c, int st, int tile) {
    const int tid = threadIdx.x, warp = tid >> 5, lane = tid & 31;
    __half* Hs = (__half*)(sm + OFF_DYN + st * F_STG_B);
    __half* Bw = Hs + 64 * HLD + warp * (16 * BLD);
    const int k0 = c * 16;
    if (tid < 128) {
        int r = tid >> 1, g = tid & 1;
        cpa16(Hs + r * HLD + g * 8, g_h16 + r * HID + k0 + g * 8);
    }
    {
        int cc = lane >> 1, g = lane & 1;
        cpa16(Bw + cc * BLD + g * 8,
              g_W16 + (size_t)(tile * 16 + cc) * HID + k0 + g * 8);
    }
    cp_commit();
}

__device__ __forceinline__ void fc_step_dev(char* sm, int t, const float* fcb,
                                            float* __restrict__ out) {
    const int tid = threadIdx.x, cta = blockIdx.x;
    const int warp = tid >> 5, lane = tid & 31;

    if (cta >= 125) {
        if (tid < 64) g_pmax[cta * 64 + tid] = 0u;
        return;
    }
    const int tile = cta * 16 + warp;

    wmma::fragment<wmma::accumulator, 16, 16, 16, float> acc[4];
    #pragma unroll
    for (int m = 0; m < 4; m++) wmma::fill_fragment(acc[m], 0.f);

    fc_issue(sm, 0, 0, tile);
    fc_issue(sm, 1, 1, tile);
    fc_issue(sm, 2, 2, tile);
    for (int c = 0; c < 64; c++) {
        if (c < 62) cp_wait<2>();
        else if (c == 62) cp_wait<1>();
        else cp_wait<0>();
        __syncthreads();
        if (c + 3 < 64) fc_issue(sm, c + 3, (c + 3) & 3, tile);
        __half* Hs = (__half*)(sm + OFF_DYN + (c & 3) * F_STG_B);
        __half* Bw = Hs + 64 * HLD + warp * (16 * BLD);
        wmma::fragment<wmma::matrix_b, 16, 16, 16, __half, wmma::col_major> b0;
        wmma::load_matrix_sync(b0, Bw, BLD);
        #pragma unroll
        for (int m = 0; m < 4; m++) {
            wmma::fragment<wmma::matrix_a, 16, 16, 16, __half, wmma::row_major> a;
            wmma::load_matrix_sync(a, Hs + m * 16 * HLD, HLD);
            wmma::mma_sync(acc[m], a, b0, acc[m]);
        }
    }
    __syncthreads();   // stages free -> patch + rowmax

    float* patch = (float*)(sm + OFF_DYN) + warp * 16 * PLD;
    unsigned* srm = (unsigned*)((float*)(sm + OFF_DYN) + 16 * 16 * PLD);
    if (tid < 64) srm[tid] = 0u;
    __syncthreads();

    const int col0 = tile * 16;
    #pragma unroll
    for (int m = 0; m < 4; m++) {
        wmma::store_matrix_sync(patch, acc[m], PLD, wmma::mem_row_major);
        __syncwarp();
        #pragma unroll
        for (int e8 = 0; e8 < 8; e8++) {
            int e = lane + e8 * 32;
            int r = e >> 4, cc = e & 15;
            float val = patch[r * PLD + cc] + fcb[col0 + cc];
            out[((size_t)t * 64 + m * 16 + r) * VOC + col0 + cc] = val;
            float v = val;
            #pragma unroll
            for (int o = 8; o > 0; o >>= 1)
                v = fmaxf(v, __shfl_xor_sync(0xffffffffu, v, o));
            if ((lane & 15) == 0) atomicMax(&srm[m * 16 + r], fenc(v));
        }
        __syncwarp();
    }
    __syncthreads();
    if (tid < 64) g_pmax[cta * 64 + tid] = srm[tid];
}

// ---------------- argmax + x staging (prologue of next lstm phase, CTAs<64) ----------------
__device__ __forceinline__ void argmax_stage(char* sm, int t, int p,
        const float* fcW, const float* fcb, const float* dec_emb,
        const float* __restrict__ out) {
    const int cta = blockIdx.x, tid = threadIdx.x;
    const int row = cta;

    unsigned* spm  = (unsigned*)(sm + OFF_DYN);          // 128
    unsigned* sgm  = spm + 128;
    int* snc   = (int*)(sgm + 1);
    int* scnt  = snc + 1;
    int* stok  = scnt + 1;
    int* secta = stok + 1;                               // 128
    int* cand  = secta + 128;                            // 512

    if (tid < 128) spm[tid] = __ldcg(&g_pmax[tid * 64 + row]);
    if (tid == 0) { *snc = 0; *scnt = 0; }
    __syncthreads();
    if (tid < 32) {
        unsigned k = spm[tid];
        k = max(k, spm[tid + 32]);
        k = max(k, spm[tid + 64]);
        k = max(k, spm[tid + 96]);
        #pragma unroll
        for (int o = 16; o > 0; o >>= 1)
            k = max(k, __shfl_xor_sync(0xffffffffu, k, o));
        if (tid == 0) *sgm = k;
    }
    __syncthreads();
    const float th = fdec(*sgm) - 0.02f;

    if (tid < 128 && fdec(spm[tid]) >= th) {
        int e = atomicAdd(snc, 1);
        secta[e] = tid;
    }
    __syncthreads();
    int ne = *snc;

    const float* lg = out + ((size_t)t * 64 + row) * VOC;
    for (int e = 0; e < ne; e += 2) {
        int idx = e + (tid >> 8);
        if (idx < ne) {
            int c = secta[idx];
            int col = c * 256 + (tid & 255);
            float x = __ldcg(lg + col);
            if (x >= th) {
                int pp = atomicAdd(scnt, 1);
                if (pp < 512) cand[pp] = col;
            }
        }
    }
    __syncthreads();
    int n = *scnt; if (n > 512) n = 512;

    if (tid < 32) {
        const float* hr = g_h[p] + row * HID;
        float bestv = -3.4e38f; int besti = 0x7fffffff;
        for (int ci = 0; ci < n; ci++) {
            int v = cand[ci];
            const float* wr = fcW + (size_t)v * HID;
            float s = 0.f;
            for (int k = tid; k < HID; k += 32) s += __ldcg(hr + k) * wr[k];
            #pragma unroll
            for (int o = 16; o > 0; o >>= 1) s += __shfl_xor_sync(0xffffffffu, s, o);
            s += fcb[v];
            if (s > bestv || (s == bestv && v < besti)) { bestv = s; besti = v; }
        }
        if (tid == 0) *stok = besti;
    }
    __syncthreads();
    int tok = *stok;
    __nv_bfloat16* oAh = g_A_hi[p];     // x part of the buffer lstm(d) consumes
    __nv_bfloat16* oAl = g_A_lo[p];
    for (int k = tid; k < EMB; k += NTHR) {
        float v = dec_emb[(size_t)tok * EMB + k];
        __nv_bfloat16 hi = __float2bfloat16(v);
        oAh[cta * KC + k] = hi;
        oAl[cta * KC + k] = __float2bfloat16(v - __bfloat162float(hi));
    }
    __threadfence();
    __syncthreads();
    if (tid == 0) red_add_rel(&g_xcnt, 1u);
}

// ---------------- persistent kernel ----------------
__global__ void __launch_bounds__(NTHR, 1) persist(
        const int* __restrict__ src, const int* __restrict__ trg,
        const float* __restrict__ enc_emb, const float* __restrict__ dec_emb,
        const float* __restrict__ fcW, const float* __restrict__ fcb,
        float* __restrict__ out) {
    extern __shared__ char sm[];
    const int tid = threadIdx.x, cta = blockIdx.x;
    float* sC = (float*)(sm + OFF_C);
    unsigned gen = 0;

    sC[tid] = 0.f;

    load_weights_dev(sm, 0);

    if (cta < 64) {
        int tok = src[cta];
        for (int k = tid; k < EMB; k += NTHR) {
            float v = enc_emb[(size_t)tok * EMB + k];
            __nv_bfloat16 hi = __float2bfloat16(v);
            g_A_hi[0][cta * KC + k] = hi;
            g_A_lo[0][cta * KC + k] = __float2bfloat16(v - __bfloat162float(hi));
        }
    }
    gbar(++gen);

    // ---- encoder ----
    for (int s = 0; s < SRCLEN; s++) {
        int ntok = -1;
        const float* nemb = enc_emb;
        if (cta < 64) {
            if (s < SRCLEN - 1) { ntok = src[(s + 1) * BATCH + cta]; nemb = enc_emb; }
            else                { ntok = trg[cta];                   nemb = dec_emb; }
        }
        lstm_step_dev(sm, s & 1, 0, ntok, nemb, 0);
        gbar(++gen);
    }

    load_weights_dev(sm, 1);

    // ---- decoder: per step = [argmax(prev) + lstm] bar [fc] bar ----
    for (int d = 0; d < TRGLEN - 1; d++) {
        int p = d & 1;                 // (SRCLEN + d) & 1, SRCLEN even
        if (d > 0 && cta < 64)
            argmax_stage(sm, d, p, fcW, fcb, dec_emb, out);
        lstm_step_dev(sm, p, 1, -1, dec_emb, d);
        gbar(++gen);
        fc_step_dev(sm, d + 1, fcb, out);
        gbar(++gen);
    }
}

// ---------------- launch ----------------
extern "C" void kernel_launch(void* const* d_in, const int* in_sizes, int n_in,
                              void* d_out, int out_size) {
    const int*   src     = (const int*)  d_in[0];
    const int*   trg     = (const int*)  d_in[1];
    const float* enc_emb = (const float*)d_in[2];
    const float* eWih    = (const float*)d_in[3];
    const float* eWhh    = (const float*)d_in[4];
    const float* ebih    = (const float*)d_in[5];
    const float* ebhh    = (const float*)d_in[6];
    const float* dec_emb = (const float*)d_in[7];
    const float* dWih    = (const float*)d_in[8];
    const float* dWhh    = (const float*)d_in[9];
    const float* dbih    = (const float*)d_in[10];
    const float* dbhh    = (const float*)d_in[11];
    const float* fcW     = (const float*)d_in[12];
    const float* fcb     = (const float*)d_in[13];
    float* out = (float*)d_out;

    prep_fc<<<2048, 256>>>(fcW);
    prep_lstm<<<2048, 256>>>(eWih, eWhh, ebih, ebhh, dWih, dWhh, dbih, dbhh);
    init_k<<<2048, 256>>>(out);

    cudaFuncSetAttribute(persist, cudaFuncAttributeMaxDynamicSharedMemorySize, SMEM_TOTAL);
    persist<<<NCTA, NTHR, SMEM_TOTAL>>>(src, trg, enc_emb, dec_emb, fcW, fcb, out);
}